// round 1
// baseline (speedup 1.0000x reference)
#include <cuda_runtime.h>
#include <cstdint>

typedef unsigned long long ull;

// ---------------------------------------------------------------------------
// Packed fp32x2 helpers (Blackwell f32x2 pipe; ptxas will not auto-fuse these)
// ---------------------------------------------------------------------------
__device__ __forceinline__ ull pack2(float x, float y) {
    ull r; asm("mov.b64 %0, {%1,%2};" : "=l"(r) : "f"(x), "f"(y)); return r;
}
__device__ __forceinline__ float2 unpack2(ull v) {
    float2 r; asm("mov.b64 {%0,%1}, %2;" : "=f"(r.x), "=f"(r.y) : "l"(v)); return r;
}
__device__ __forceinline__ ull fma2(ull a, ull b, ull c) {
    ull d; asm("fma.rn.f32x2 %0, %1, %2, %3;" : "=l"(d) : "l"(a), "l"(b), "l"(c)); return d;
}

// ---------------------------------------------------------------------------
// Problem constants
// ---------------------------------------------------------------------------
#define NPAIRS 64      // B*heads = 8*8
#define NSEQ   4096    // H*W
#define DD     64      // head_dim

// Kernel 1 (KV pass)
#define SPLITS 16
#define TILE1  128
#define RS1    130     // 128 + 2 pad floats -> bank-pair stride 65 (==1 mod 16)
#define TILES1 2       // 4096 / SPLITS / TILE1

// Kernel 2 (Q/output pass)
#define TILE2  256
#define RS2    258

// Scratch (device globals: no allocations allowed)
__device__ float g_scratch[NPAIRS * SPLITS * DD * DD];  // 16 MB
__device__ float g_kv[NPAIRS * DD * DD];                // 1 MB

// ---------------------------------------------------------------------------
// Kernel 1: per (pair, split): KF = relu(Wf@Ktile + b); KVpartial += KF @ V^T
// ---------------------------------------------------------------------------
__global__ void __launch_bounds__(256, 2)
k_kvpass(const float* __restrict__ K, const float* __restrict__ V,
         const float* __restrict__ Wf, const float* __restrict__ bf)
{
    extern __shared__ float sm1[];
    float* Ks  = sm1;                 // 64 * RS1  (K tile, then overwritten by KF)
    float* Vs  = Ks + 64 * RS1;       // 64 * RS1
    float* Wfs = Vs + 64 * RS1;       // 4096
    float* bfs = Wfs + 4096;          // 64

    const int p     = blockIdx.y;
    const int split = blockIdx.x;
    const int t     = threadIdx.x;
    const int w     = t >> 5;
    const int l     = t & 31;

    for (int i = t; i < 4096; i += 256) Wfs[i] = Wf[i];
    if (t < 64) bfs[t] = bf[t];

    const float* Kb = K + (size_t)p * DD * NSEQ;
    const float* Vb = V + (size_t)p * DD * NSEQ;

    // phase-2 output mapping: KV[e][e2], e = eg + 16i, e2 = e2g + 16j
    const int eg  = t >> 4;   // 0..15
    const int e2g = t & 15;   // 0..15

    ull kvacc[4][4];
    #pragma unroll
    for (int i = 0; i < 4; ++i)
        #pragma unroll
        for (int j = 0; j < 4; ++j) kvacc[i][j] = 0ull;

    for (int tile = 0; tile < TILES1; ++tile) {
        const int n0 = split * (TILE1 * TILES1) + tile * TILE1;
        __syncthreads();  // protect Ks/Vs reuse (covers Wfs/bfs init on iter 0)

        // cooperative coalesced tile load: 64 rows x 128 cols, float4 gmem reads
        for (int m = t; m < 64 * 32; m += 256) {
            const int row = m >> 5;
            const int c4  = (m & 31) << 2;
            float4 kk = *(const float4*)(Kb + row * NSEQ + n0 + c4);
            float4 vv = *(const float4*)(Vb + row * NSEQ + n0 + c4);
            float2* dk = (float2*)&Ks[row * RS1 + c4];
            dk[0] = make_float2(kk.x, kk.y);
            dk[1] = make_float2(kk.z, kk.w);
            float2* dv = (float2*)&Vs[row * RS1 + c4];
            dv[0] = make_float2(vv.x, vv.y);
            dv[1] = make_float2(vv.z, vv.w);
        }
        __syncthreads();

        // phase 1: KF[e][n] = relu(sum_d Wf[e][d]*K[d][n] + b[e])
        // thread tile: e = w*8 + i, n = 2l + 64j (j=0..1)
        ull acc1[8][2];
        #pragma unroll
        for (int i = 0; i < 8; ++i) { acc1[i][0] = 0ull; acc1[i][1] = 0ull; }

        #pragma unroll 4
        for (int d = 0; d < 64; ++d) {
            const ull b0 = *(const ull*)&Ks[d * RS1 + 2 * l];
            const ull b1 = *(const ull*)&Ks[d * RS1 + 64 + 2 * l];
            #pragma unroll
            for (int i = 0; i < 8; ++i) {
                const float a  = Wfs[(w * 8 + i) * 64 + d];
                const ull   a2 = pack2(a, a);
                acc1[i][0] = fma2(a2, b0, acc1[i][0]);
                acc1[i][1] = fma2(a2, b1, acc1[i][1]);
            }
        }
        __syncthreads();  // everyone done reading Ks
        #pragma unroll
        for (int i = 0; i < 8; ++i) {
            const float bb = bfs[w * 8 + i];
            #pragma unroll
            for (int j = 0; j < 2; ++j) {
                float2 x = unpack2(acc1[i][j]);
                x.x = fmaxf(x.x + bb, 0.f);
                x.y = fmaxf(x.y + bb, 0.f);
                *(float2*)&Ks[(w * 8 + i) * RS1 + 64 * j + 2 * l] = x;  // KF in-place
            }
        }
        __syncthreads();

        // phase 2: KV[e][e2] += sum_n KF[e][n] * V[e2][n]  (n packed in pairs)
        #pragma unroll 4
        for (int np = 0; np < 64; ++np) {
            ull a2[4], b2[4];
            #pragma unroll
            for (int i = 0; i < 4; ++i)
                a2[i] = *(const ull*)&Ks[(eg + 16 * i) * RS1 + 2 * np];
            #pragma unroll
            for (int j = 0; j < 4; ++j)
                b2[j] = *(const ull*)&Vs[(e2g + 16 * j) * RS1 + 2 * np];
            #pragma unroll
            for (int i = 0; i < 4; ++i)
                #pragma unroll
                for (int j = 0; j < 4; ++j)
                    kvacc[i][j] = fma2(a2[i], b2[j], kvacc[i][j]);
        }
    }

    float* dst = g_scratch + ((size_t)p * SPLITS + split) * DD * DD;
    #pragma unroll
    for (int i = 0; i < 4; ++i)
        #pragma unroll
        for (int j = 0; j < 4; ++j) {
            float2 x = unpack2(kvacc[i][j]);
            dst[(eg + 16 * i) * DD + (e2g + 16 * j)] = x.x + x.y;
        }
}

// ---------------------------------------------------------------------------
// Kernel 2: deterministic fixed-order reduction of split partials
// ---------------------------------------------------------------------------
__global__ void k_reduce()
{
    const int idx = blockIdx.x * 256 + threadIdx.x;   // 0 .. 64*4096-1
    const int p = idx >> 12;
    const int r = idx & 4095;
    float s = 0.f;
    #pragma unroll
    for (int sp = 0; sp < SPLITS; ++sp)
        s += g_scratch[((size_t)p * SPLITS + sp) * (DD * DD) + r];
    g_kv[idx] = s;
}

// ---------------------------------------------------------------------------
// Kernel 3: QF = relu(Wf@Qtile + b); O = KV^T @ QF, written to output layout
// ---------------------------------------------------------------------------
__global__ void __launch_bounds__(256, 2)
k_qpass(const float* __restrict__ Q, const float* __restrict__ Wf,
        const float* __restrict__ bf, float* __restrict__ Out)
{
    extern __shared__ float sm2[];
    float* buf = sm2;               // 64 * RS2 (Q tile, then QF in-place)
    float* Wfs = buf + 64 * RS2;    // 4096
    float* KVs = Wfs + 4096;        // 4096
    float* bfs = KVs + 4096;        // 64

    const int p  = blockIdx.y;
    const int n0 = blockIdx.x * TILE2;
    const int t  = threadIdx.x;
    const int w  = t >> 5;
    const int l  = t & 31;

    for (int i = t; i < 4096; i += 256) {
        Wfs[i] = Wf[i];
        KVs[i] = g_kv[(size_t)p * 4096 + i];
    }
    if (t < 64) bfs[t] = bf[t];

    const float* Qb = Q + (size_t)p * DD * NSEQ;

    // load Q tile [64][256]
    for (int m = t; m < 64 * 64; m += 256) {
        const int row = m >> 6;
        const int c4  = (m & 63) << 2;
        float4 qq = *(const float4*)(Qb + row * NSEQ + n0 + c4);
        float2* dq = (float2*)&buf[row * RS2 + c4];
        dq[0] = make_float2(qq.x, qq.y);
        dq[1] = make_float2(qq.z, qq.w);
    }
    __syncthreads();

    // phase 1: QF[e][n], thread tile e = w*8+i, n = 2l + 64j (j=0..3)
    ull acc[8][4];
    #pragma unroll
    for (int i = 0; i < 8; ++i)
        #pragma unroll
        for (int j = 0; j < 4; ++j) acc[i][j] = 0ull;

    #pragma unroll 2
    for (int d = 0; d < 64; ++d) {
        ull b2[4];
        #pragma unroll
        for (int j = 0; j < 4; ++j)
            b2[j] = *(const ull*)&buf[d * RS2 + 64 * j + 2 * l];
        #pragma unroll
        for (int i = 0; i < 8; ++i) {
            const float a  = Wfs[(w * 8 + i) * 64 + d];
            const ull   a2 = pack2(a, a);
            #pragma unroll
            for (int j = 0; j < 4; ++j)
                acc[i][j] = fma2(a2, b2[j], acc[i][j]);
        }
    }
    __syncthreads();
    #pragma unroll
    for (int i = 0; i < 8; ++i) {
        const float bb = bfs[w * 8 + i];
        #pragma unroll
        for (int j = 0; j < 4; ++j) {
            float2 x = unpack2(acc[i][j]);
            x.x = fmaxf(x.x + bb, 0.f);
            x.y = fmaxf(x.y + bb, 0.f);
            *(float2*)&buf[(w * 8 + i) * RS2 + 64 * j + 2 * l] = x;  // QF in-place
        }
    }
    __syncthreads();

    // phase 2: O[e2][n] = sum_e KV[e][e2] * QF[e][n], e2 = w*8+i
    ull o[8][4];
    #pragma unroll
    for (int i = 0; i < 8; ++i)
        #pragma unroll
        for (int j = 0; j < 4; ++j) o[i][j] = 0ull;

    #pragma unroll 2
    for (int e = 0; e < 64; ++e) {
        ull b2[4];
        #pragma unroll
        for (int j = 0; j < 4; ++j)
            b2[j] = *(const ull*)&buf[e * RS2 + 64 * j + 2 * l];
        #pragma unroll
        for (int i = 0; i < 8; ++i) {
            const float a  = KVs[e * 64 + w * 8 + i];
            const ull   a2 = pack2(a, a);
            #pragma unroll
            for (int j = 0; j < 4; ++j)
                o[i][j] = fma2(a2, b2[j], o[i][j]);
        }
    }

    float* Ob = Out + (size_t)p * DD * NSEQ;
    #pragma unroll
    for (int i = 0; i < 8; ++i)
        #pragma unroll
        for (int j = 0; j < 4; ++j)
            *(float2*)(Ob + (w * 8 + i) * NSEQ + n0 + 64 * j + 2 * l) = unpack2(o[i][j]);
}

// ---------------------------------------------------------------------------
// Launch
// ---------------------------------------------------------------------------
extern "C" void kernel_launch(void* const* d_in, const int* in_sizes, int n_in,
                              void* d_out, int out_size)
{
    const float* q  = (const float*)d_in[0];
    const float* k  = (const float*)d_in[1];
    const float* v  = (const float*)d_in[2];
    const float* Wf = (const float*)d_in[3];
    const float* bf = (const float*)d_in[4];
    float* out = (float*)d_out;

    const int SMEM1 = (2 * 64 * RS1 + 4096 + 64) * (int)sizeof(float);          // ~83 KB
    const int SMEM2 = (64 * RS2 + 4096 + 4096 + 64) * (int)sizeof(float);       // ~97 KB
    cudaFuncSetAttribute(k_kvpass, cudaFuncAttributeMaxDynamicSharedMemorySize, SMEM1);
    cudaFuncSetAttribute(k_qpass,  cudaFuncAttributeMaxDynamicSharedMemorySize, SMEM2);

    k_kvpass<<<dim3(SPLITS, NPAIRS), 256, SMEM1>>>(k, v, Wf, bf);
    k_reduce<<<(NPAIRS * DD * DD) / 256, 256>>>();
    k_qpass<<<dim3(NSEQ / TILE2, NPAIRS), 256, SMEM2>>>(q, Wf, bf, out);
}